// round 5
// baseline (speedup 1.0000x reference)
#include <cuda_runtime.h>
#include <cuda_bf16.h>

// LSEP loss, factorized:
//   S_b = (sum_{neg} e^{x}) * (sum_{pos} e^{-x});  loss = mean_b log1p(S_b)
// N = 512 rows, C = 512 cols.
//
// Single kernel node, ZERO atomics. One CTA per row (proven fastest body:
// 128 threads, one float4 + one int4 per thread, 16 regs). Each CTA publishes
// its row result as a single 64-bit {flag|value} word (one STG.64 -> flag and
// value are inherently atomic together, no fence needed). All 512 CTAs are
// co-resident (occupancy capacity ~2368 CTAs), so CTA 511 spin-polls the 512
// slots with volatile 64-bit loads, sums deterministically, resets the slots
// (replay-idempotent, no memset node), and writes the scalar output.

#define NROWS 512
#define NCOLS 512

__device__ unsigned long long g_slot[NROWS];   // zero-initialized; reset each run

__global__ void __launch_bounds__(128) lsep_kernel(
    const int* __restrict__ y_true,
    const float* __restrict__ y_pred,
    float* __restrict__ out)
{
    const int row = blockIdx.x;
    const int i   = threadIdx.x;

    const float4* __restrict__ pv = reinterpret_cast<const float4*>(y_pred + row * NCOLS);
    const int4*   __restrict__ tv = reinterpret_cast<const int4*>(y_true + row * NCOLS);

    // 512 cols = 128 float4 -> exactly one vector pair per thread
    float4 v = pv[i];
    int4   l = tv[i];

    float pos = 0.f, neg = 0.f;

#define ACC(LBL, VAL) do {                          \
        float e = __expf((LBL) ? -(VAL) : (VAL));   \
        if (LBL) pos += e; else neg += e;           \
    } while (0)

    ACC(l.x, v.x);
    ACC(l.y, v.y);
    ACC(l.z, v.z);
    ACC(l.w, v.w);
#undef ACC

    // warp reduction (two independent shuffle chains)
    #pragma unroll
    for (int off = 16; off > 0; off >>= 1) {
        pos += __shfl_xor_sync(0xFFFFFFFFu, pos, off);
        neg += __shfl_xor_sync(0xFFFFFFFFu, neg, off);
    }

    __shared__ float s_pos[4];
    __shared__ float s_neg[4];
    const int wid = i >> 5;
    const int lid = i & 31;
    if (lid == 0) { s_pos[wid] = pos; s_neg[wid] = neg; }
    __syncthreads();

    if (i == 0) {
        float p = s_pos[0] + s_pos[1] + s_pos[2] + s_pos[3];
        float n = s_neg[0] + s_neg[1] + s_neg[2] + s_neg[3];
        float contrib = log1pf(p * n);
        // flag (hi 32) + value (lo 32) in ONE 64-bit store: reader sees both
        // or neither — no fence/atomic required.
        unsigned long long pack =
            (1ULL << 32) | (unsigned long long)__float_as_uint(contrib);
        *(volatile unsigned long long*)&g_slot[row] = pack;
    }

    // Reducer CTA: last launched block; all blocks are co-resident so this
    // spin cannot deadlock.
    if (row == NROWS - 1) {
        float s = 0.f;
        #pragma unroll
        for (int j = 0; j < 4; j++) {
            const int idx = i * 4 + j;
            volatile unsigned long long* p = &g_slot[idx];
            unsigned long long pk;
            do { pk = *p; } while ((pk >> 32) == 0ULL);
            s += __uint_as_float((unsigned int)pk);
            *p = 0ULL;                       // reset for next graph replay
        }

        #pragma unroll
        for (int off = 16; off > 0; off >>= 1)
            s += __shfl_xor_sync(0xFFFFFFFFu, s, off);

        __shared__ float s_part[4];
        if (lid == 0) s_part[wid] = s;
        __syncthreads();

        if (i == 0) {
            float total = s_part[0] + s_part[1] + s_part[2] + s_part[3];
            out[0] = total * (1.0f / (float)NROWS);
        }
    }
}

extern "C" void kernel_launch(void* const* d_in, const int* in_sizes, int n_in,
                              void* d_out, int out_size)
{
    const int*   y_true = (const int*)d_in[0];
    const float* y_pred = (const float*)d_in[1];
    float* out = (float*)d_out;

    lsep_kernel<<<NROWS, 128>>>(y_true, y_pred, out);
}

// round 7
// speedup vs baseline: 1.2546x; 1.2546x over previous
#include <cuda_runtime.h>
#include <cuda_bf16.h>

// LSEP loss, factorized:
//   S_b = (sum_{neg} e^{x}) * (sum_{pos} e^{-x});  loss = mean_b log1p(S_b)
// N = 512 rows, C = 512 cols.
//
// Single kernel node. One CTA per row (proven fastest body: 128 threads, one
// float4 + one int4 per thread). Cross-CTA combine = ONE 64-bit integer
// atomicAdd per CTA into g_pack:
//   bits [52..62) : arrival count (each CTA adds 1<<52)
//   bits [0..52)  : fixed-point sum of log1p(S_row), scale 2^26
// Integer adds are associative -> deterministic. The CTA whose returned
// prev-count == 511 is last: it publishes out[0] and resets g_pack with a
// single atomicExch (replay-idempotent, no memset node, no fences).

#define NROWS 512
#define NCOLS 512

#define CNT_ONE  (1ULL << 52)
#define VAL_MASK (CNT_ONE - 1ULL)
#define FP_SCALE 67108864.0   // 2^26

__device__ unsigned long long g_pack;   // zero-initialized; reset each run

__global__ void __launch_bounds__(128) lsep_kernel(
    const int* __restrict__ y_true,
    const float* __restrict__ y_pred,
    float* __restrict__ out)
{
    const int row = blockIdx.x;
    const int i   = threadIdx.x;

    const float4* __restrict__ pv = reinterpret_cast<const float4*>(y_pred + row * NCOLS);
    const int4*   __restrict__ tv = reinterpret_cast<const int4*>(y_true + row * NCOLS);

    // 512 cols = 128 float4 -> exactly one vector pair per thread
    float4 v = pv[i];
    int4   l = tv[i];

    float pos = 0.f, neg = 0.f;

#define ACC(LBL, VAL) do {                          \
        float e = __expf((LBL) ? -(VAL) : (VAL));   \
        if (LBL) pos += e; else neg += e;           \
    } while (0)

    ACC(l.x, v.x);
    ACC(l.y, v.y);
    ACC(l.z, v.z);
    ACC(l.w, v.w);
#undef ACC

    // warp reduction (two independent shuffle chains)
    #pragma unroll
    for (int off = 16; off > 0; off >>= 1) {
        pos += __shfl_xor_sync(0xFFFFFFFFu, pos, off);
        neg += __shfl_xor_sync(0xFFFFFFFFu, neg, off);
    }

    __shared__ float s_pos[4];
    __shared__ float s_neg[4];
    const int wid = i >> 5;
    const int lid = i & 31;
    if (lid == 0) { s_pos[wid] = pos; s_neg[wid] = neg; }
    __syncthreads();

    if (i == 0) {
        float p = s_pos[0] + s_pos[1] + s_pos[2] + s_pos[3];
        float n = s_neg[0] + s_neg[1] + s_neg[2] + s_neg[3];
        float contrib = log1pf(p * n);              // >= 0 always

        // Fixed-point encode (double for exact scaling; 1 op per CTA, cheap)
        unsigned long long fx =
            (unsigned long long)((double)contrib * FP_SCALE);
        unsigned long long prev = atomicAdd(&g_pack, CNT_ONE | fx);

        if ((prev >> 52) == (unsigned long long)(NROWS - 1)) {
            // We are the last arrival; prev holds everyone else's sum.
            unsigned long long total_fx = (prev & VAL_MASK) + fx;
            double total = (double)total_fx * (1.0 / FP_SCALE);
            out[0] = (float)(total * (1.0 / (double)NROWS));
            atomicExch(&g_pack, 0ULL);              // reset for next replay
        }
    }
}

extern "C" void kernel_launch(void* const* d_in, const int* in_sizes, int n_in,
                              void* d_out, int out_size)
{
    const int*   y_true = (const int*)d_in[0];
    const float* y_pred = (const float*)d_in[1];
    float* out = (float*)d_out;

    lsep_kernel<<<NROWS, 128>>>(y_true, y_pred, out);
}

// round 9
// speedup vs baseline: 1.2605x; 1.0047x over previous
#include <cuda_runtime.h>
#include <cuda_bf16.h>

// LSEP loss, factorized:
//   S_b = (sum_{neg} e^{x}) * (sum_{pos} e^{-x});  loss = mean_b log1p(S_b)
// N = 512 rows, C = 512 cols.
//
// Single kernel node. 128 CTAs x 512 threads (4 rows per CTA) to cut the CTA
// dispatch ramp 4x vs grid=512, while keeping the proven per-thread shape:
// exactly one float4 + one int4 load per thread (16-reg class, max MLP).
// Cross-CTA combine = ONE 64-bit integer atomicAdd per CTA into g_pack:
//   bits [52..62) : arrival count (each CTA adds 1<<52; target 127)
//   bits [0..52)  : fixed-point sum of log1p(S_row), scale 2^26
// Deterministic (integer adds). Last CTA publishes out[0] and resets g_pack
// with one atomicExch (replay-idempotent, no memset node, no fences).

#define NROWS 512
#define NCOLS 512
#define ROWS_PER_CTA 4
#define NBLOCKS (NROWS / ROWS_PER_CTA)   // 128
#define NTHREADS (128 * ROWS_PER_CTA)    // 512

#define CNT_ONE  (1ULL << 52)
#define VAL_MASK (CNT_ONE - 1ULL)
#define FP_SCALE 67108864.0   // 2^26

__device__ unsigned long long g_pack;   // zero-initialized; reset each run

__global__ void __launch_bounds__(NTHREADS) lsep_kernel(
    const int* __restrict__ y_true,
    const float* __restrict__ y_pred,
    float* __restrict__ out)
{
    const int t        = threadIdx.x;
    const int row_loc  = t >> 7;                 // 0..3 within CTA
    const int idx      = t & 127;                // float4 index within row
    const int row      = blockIdx.x * ROWS_PER_CTA + row_loc;

    const float4* __restrict__ pv = reinterpret_cast<const float4*>(y_pred + row * NCOLS);
    const int4*   __restrict__ tv = reinterpret_cast<const int4*>(y_true + row * NCOLS);

    // exactly one vector pair per thread
    float4 v = pv[idx];
    int4   l = tv[idx];

    float pos = 0.f, neg = 0.f;

#define ACC(LBL, VAL) do {                          \
        float e = __expf((LBL) ? -(VAL) : (VAL));   \
        if (LBL) pos += e; else neg += e;           \
    } while (0)

    ACC(l.x, v.x);
    ACC(l.y, v.y);
    ACC(l.z, v.z);
    ACC(l.w, v.w);
#undef ACC

    // warp reduction (two independent shuffle chains)
    #pragma unroll
    for (int off = 16; off > 0; off >>= 1) {
        pos += __shfl_xor_sync(0xFFFFFFFFu, pos, off);
        neg += __shfl_xor_sync(0xFFFFFFFFu, neg, off);
    }

    __shared__ float s_pos[16];
    __shared__ float s_neg[16];
    const int wid  = t >> 5;    // 0..15 (warps 4r..4r+3 belong to row r)
    const int lane = t & 31;
    if (lane == 0) { s_pos[wid] = pos; s_neg[wid] = neg; }
    __syncthreads();

    if (wid == 0) {
        // lanes 0..3 each finalize one row; other lanes contribute 0
        float contrib = 0.f;
        if (lane < ROWS_PER_CTA) {
            const int r4 = lane * 4;
            float p = s_pos[r4] + s_pos[r4 + 1] + s_pos[r4 + 2] + s_pos[r4 + 3];
            float n = s_neg[r4] + s_neg[r4 + 1] + s_neg[r4 + 2] + s_neg[r4 + 3];
            contrib = log1pf(p * n);
        }
        // sum lanes 0..3 into lane 0 (xor-reduce over offsets 2,1)
        contrib += __shfl_xor_sync(0xFFFFFFFFu, contrib, 2);
        contrib += __shfl_xor_sync(0xFFFFFFFFu, contrib, 1);

        if (lane == 0) {
            unsigned long long fx =
                (unsigned long long)((double)contrib * FP_SCALE);
            unsigned long long prev = atomicAdd(&g_pack, CNT_ONE | fx);

            if ((prev >> 52) == (unsigned long long)(NBLOCKS - 1)) {
                unsigned long long total_fx = (prev & VAL_MASK) + fx;
                double total = (double)total_fx * (1.0 / FP_SCALE);
                out[0] = (float)(total * (1.0 / (double)NROWS));
                atomicExch(&g_pack, 0ULL);          // reset for next replay
            }
        }
    }
}

extern "C" void kernel_launch(void* const* d_in, const int* in_sizes, int n_in,
                              void* d_out, int out_size)
{
    const int*   y_true = (const int*)d_in[0];
    const float* y_pred = (const float*)d_in[1];
    float* out = (float*)d_out;

    lsep_kernel<<<NBLOCKS, NTHREADS>>>(y_true, y_pred, out);
}

// round 10
// speedup vs baseline: 1.3969x; 1.1082x over previous
#include <cuda_runtime.h>
#include <cuda_bf16.h>

// LSEP loss, factorized:
//   S_b = (sum_{neg} e^{x}) * (sum_{pos} e^{-x});  loss = mean_b log1p(S_b)
// N = 512 rows, C = 512 cols.
//
// Single kernel node. 128 CTAs x 512 threads (4 rows per CTA); exactly one
// float4 + one int4 load per thread. Cross-CTA combine = ONE 64-bit integer
// atomicAdd per CTA into g_pack:
//   bits [52..62) : arrival count (each CTA adds 1<<52; target 127)
//   bits [0..52)  : fixed-point sum of log1p(S_row), scale 2^26
// Deterministic (integer adds). Last CTA publishes out[0]; reset is a plain
// store (no CTA touches g_pack after the count saturates). Replay-idempotent.
//
// Micro-trims vs prev round (all on the serial critical path):
//  - branchless sign flip via XOR of the sign bit (no select before MUFU)
//  - all-float fixed-point encode (no fp64 on the publish path)
//  - __logf(1+s) instead of software log1pf
//  - plain store reset instead of atomicExch

#define NROWS 512
#define NCOLS 512
#define ROWS_PER_CTA 4
#define NBLOCKS (NROWS / ROWS_PER_CTA)   // 128
#define NTHREADS (128 * ROWS_PER_CTA)    // 512

#define CNT_ONE  (1ULL << 52)
#define VAL_MASK (CNT_ONE - 1ULL)
#define FP_SCALE 67108864.0f   // 2^26

__device__ unsigned long long g_pack;   // zero-initialized; reset each run

__global__ void __launch_bounds__(NTHREADS) lsep_kernel(
    const int* __restrict__ y_true,
    const float* __restrict__ y_pred,
    float* __restrict__ out)
{
    const int t       = threadIdx.x;
    const int row_loc = t >> 7;                 // 0..3 within CTA
    const int idx     = t & 127;                // float4 index within row
    const int row     = blockIdx.x * ROWS_PER_CTA + row_loc;

    const float4* __restrict__ pv = reinterpret_cast<const float4*>(y_pred + row * NCOLS);
    const int4*   __restrict__ tv = reinterpret_cast<const int4*>(y_true + row * NCOLS);

    float4 v = pv[idx];
    int4   l = tv[idx];

    float pos = 0.f, neg = 0.f;

    // Branchless: flip sign of v when label==1, exp once, route to pos/neg.
#define ACC(LBL, VAL) do {                                              \
        float x = __int_as_float(__float_as_int(VAL) ^ ((LBL) << 31));  \
        float e = __expf(x);                                            \
        float fl = (float)(LBL);                                        \
        pos = fmaf(fl, e, pos);                                         \
        neg = fmaf(1.0f - fl, e, neg);                                  \
    } while (0)

    ACC(l.x, v.x);
    ACC(l.y, v.y);
    ACC(l.z, v.z);
    ACC(l.w, v.w);
#undef ACC

    // warp reduction (two independent shuffle chains, pipelined)
    #pragma unroll
    for (int off = 16; off > 0; off >>= 1) {
        pos += __shfl_xor_sync(0xFFFFFFFFu, pos, off);
        neg += __shfl_xor_sync(0xFFFFFFFFu, neg, off);
    }

    __shared__ float s_pos[16];
    __shared__ float s_neg[16];
    const int wid  = t >> 5;    // warps 4r..4r+3 belong to row r
    const int lane = t & 31;
    if (lane == 0) { s_pos[wid] = pos; s_neg[wid] = neg; }
    __syncthreads();

    if (wid == 0) {
        // lanes 0..3 each finalize one row; other lanes contribute 0
        float contrib = 0.f;
        if (lane < ROWS_PER_CTA) {
            const int r4 = lane * 4;
            float p = s_pos[r4] + s_pos[r4 + 1] + s_pos[r4 + 2] + s_pos[r4 + 3];
            float n = s_neg[r4] + s_neg[r4 + 1] + s_neg[r4 + 2] + s_neg[r4 + 3];
            contrib = __logf(1.0f + p * n);
        }
        contrib += __shfl_xor_sync(0xFFFFFFFFu, contrib, 2);
        contrib += __shfl_xor_sync(0xFFFFFFFFu, contrib, 1);

        if (lane == 0) {
            // fixed-point encode in fp32 (contrib*2^26 < 2^31, exact enough:
            // quantization ~5e-7 absolute per row)
            unsigned long long fx = (unsigned long long)(contrib * FP_SCALE);
            unsigned long long prev = atomicAdd(&g_pack, CNT_ONE | fx);

            if ((prev >> 52) == (unsigned long long)(NBLOCKS - 1)) {
                unsigned long long total_fx = (prev & VAL_MASK) + fx;
                float total = (float)total_fx * (1.0f / FP_SCALE);
                out[0] = total * (1.0f / (float)NROWS);
                // No other CTA touches g_pack after count saturation:
                // plain store reset is race-free and cheaper than atomicExch.
                *(volatile unsigned long long*)&g_pack = 0ULL;
            }
        }
    }
}

extern "C" void kernel_launch(void* const* d_in, const int* in_sizes, int n_in,
                              void* d_out, int out_size)
{
    const int*   y_true = (const int*)d_in[0];
    const float* y_pred = (const float*)d_in[1];
    float* out = (float*)d_out;

    lsep_kernel<<<NBLOCKS, NTHREADS>>>(y_true, y_pred, out);
}